// round 3
// baseline (speedup 1.0000x reference)
#include <cuda_runtime.h>

// GAE: advantages/targets, B=4096 rows, T=8192 timesteps.
// delta_t = r_t + GAMMA * v_{t+1} - v_t
// A_t = delta_t + COEF * A_{t+1}   (reverse scan, COEF = GAMMA*LAMBDA)
// targets_t = v_t + A_t
// Output layout: [advantages (B*T) | targets (B*T)] float32.
//
// R3: lane-consecutive (fully coalesced) global access in both memory phases
// (fixes 5x L1 wavefront inflation of strided scalar value loads in R2),
// shuffle-based two-level affine scan (4 barriers instead of ~20).

constexpr int   B_CONST  = 4096;
constexpr int   T_CONST  = 8192;
constexpr float GAMMA    = 0.99f;
constexpr float COEF     = 0.99f * 0.95f;           // gamma * lambda
constexpr int   THREADS  = 512;
constexpr int   NWARP    = THREADS / 32;            // 16
constexpr int   SEG      = T_CONST / THREADS;       // 16 elements per thread
constexpr int   NITER    = T_CONST / THREADS;       // 16 coalesced iters
constexpr int   TPAD     = T_CONST + T_CONST / 32;  // +1 pad float per 32

__device__ __forceinline__ int padi(int t) { return t + (t >> 5); }

__global__ __launch_bounds__(THREADS, 4)
void gae_kernel(const float* __restrict__ rewards,
                const float* __restrict__ values,
                float* __restrict__ adv_out,
                float* __restrict__ tgt_out)
{
    extern __shared__ float D[];          // TPAD floats: deltas -> advantages
    __shared__ float wa[NWARP];           // per-warp scan summaries (a)
    __shared__ float wm[NWARP];           // per-warp scan summaries (m)
    __shared__ float wcarry[NWARP];       // per-warp incoming carry

    const int row  = blockIdx.x;
    const int tid  = threadIdx.x;
    const int lane = tid & 31;
    const int wid  = tid >> 5;
    const float* r = rewards + (size_t)row * T_CONST;
    const float* v = values  + (size_t)row * (T_CONST + 1);

    // ── Phase 1: fully coalesced loads, delta into padded smem.
    // v[t] and v[t+1] are two coalesced streams sharing cache lines.
    #pragma unroll 4
    for (int i = 0; i < NITER; ++i) {
        int t = tid + i * THREADS;
        float vt  = __ldg(v + t);
        float vt1 = __ldg(v + t + 1);
        float rt  = __ldg(r + t);
        D[padi(t)] = rt + GAMMA * vt1 - vt;   // consecutive t -> conflict-free
    }
    __syncthreads();

    // ── Phase 2: per-thread local reverse scan of contiguous SEG segment,
    // zero carry -> affine summary (a, m = COEF^SEG).
    const int base = tid * SEG;
    float a = 0.0f;
    #pragma unroll
    for (int k = SEG - 1; k >= 0; --k)
        a = D[padi(base + k)] + COEF * a;

    float m = COEF;                        // COEF^16 via 4 squarings
    m *= m; m *= m; m *= m; m *= m;

    // ── Phase 3a: warp-level REVERSE inclusive scan of affine maps (shuffle).
    // After this, (a,m) at lane l = composition of segments l..31 of this warp.
    #pragma unroll
    for (int d = 1; d < 32; d <<= 1) {
        float a2 = __shfl_down_sync(0xffffffffu, a, d);
        float m2 = __shfl_down_sync(0xffffffffu, m, d);
        if (lane + d < 32) { a = a + m * a2; m = m * m2; }
    }
    if (lane == 0) { wa[wid] = a; wm[wid] = m; }   // whole-warp summary
    __syncthreads();

    // ── Phase 3b: warp 0 scans the 16 warp summaries, emits per-warp carries.
    if (wid == 0 && lane < NWARP) {
        float A = wa[lane], M = wm[lane];
        #pragma unroll
        for (int d = 1; d < NWARP; d <<= 1) {
            float A2 = __shfl_down_sync(0x0000ffffu, A, d, NWARP);
            float M2 = __shfl_down_sync(0x0000ffffu, M, d, NWARP);
            if (lane + d < NWARP) { A = A + M * A2; M = M * M2; }
        }
        float c = __shfl_down_sync(0x0000ffffu, A, 1, NWARP);  // inclusive at lane+1
        wcarry[lane] = (lane == NWARP - 1) ? 0.0f : c;
    }
    __syncthreads();

    // ── Carry entering this thread's segment = inclusive scan starting at tid+1.
    const float carryW = wcarry[wid];
    float an = __shfl_down_sync(0xffffffffu, a, 1);
    float mn = __shfl_down_sync(0xffffffffu, m, 1);
    const float carry = (lane == 31) ? carryW : an + mn * carryW;

    // ── Phase 4: exact sequential recurrence within segment, seeded with carry.
    float acc = carry;
    #pragma unroll
    for (int k = SEG - 1; k >= 0; --k) {
        int p = padi(base + k);
        acc = D[p] + COEF * acc;
        D[p] = acc;                        // delta -> advantage
    }
    __syncthreads();

    // ── Phase 5: fully coalesced scalar output; values re-read hits L2/L1.
    float* arow = adv_out + (size_t)row * T_CONST;
    float* trow = tgt_out + (size_t)row * T_CONST;
    #pragma unroll 4
    for (int i = 0; i < NITER; ++i) {
        int t = tid + i * THREADS;
        float av = D[padi(t)];
        float vt = __ldg(v + t);
        arow[t] = av;
        trow[t] = vt + av;
    }
}

extern "C" void kernel_launch(void* const* d_in, const int* in_sizes, int n_in,
                              void* d_out, int out_size)
{
    const float* rewards = (const float*)d_in[0];   // [B, T]
    const float* values  = (const float*)d_in[1];   // [B, T+1]
    float* adv = (float*)d_out;                     // [B, T]
    float* tgt = adv + (size_t)B_CONST * T_CONST;   // [B, T]

    const int smem_bytes = TPAD * (int)sizeof(float);  // ~33 KB
    cudaFuncSetAttribute(gae_kernel, cudaFuncAttributeMaxDynamicSharedMemorySize, smem_bytes);

    gae_kernel<<<B_CONST, THREADS, smem_bytes>>>(rewards, values, adv, tgt);
}